// round 17
// baseline (speedup 1.0000x reference)
#include <cuda_runtime.h>
#include <math.h>

#define R_TOT 2048   // B*C rows
#define N0 8192
#define M1 4099
#define M2 2053
#define M3 1030
#define M4 518
#define M1P 4100
#define M2P 2056
#define M3P 1032
#define M4P 520
#define CB 64
#define BB 32

__constant__ float c_dlo[8] = {-0.010597401784997278f, 0.032883011666982945f, 0.030841381835986965f,
                               -0.18703481171888114f, -0.02798376941698385f, 0.6308807679295904f,
                               0.7148465705525415f, 0.23037781330885523f};
__constant__ float c_dhi[8] = {-0.23037781330885523f, 0.7148465705525415f, -0.6308807679295904f,
                               -0.02798376941698385f, 0.18703481171888114f, 0.030841381835986965f,
                               -0.032883011666982945f, -0.010597401784997278f};
// packed (dlo[j], dhi[j]) pairs for f32x2 math
__constant__ float2 c_lh[8] = {
    {-0.010597401784997278f, -0.23037781330885523f},
    {0.032883011666982945f,  0.7148465705525415f},
    {0.030841381835986965f,  -0.6308807679295904f},
    {-0.18703481171888114f,  -0.02798376941698385f},
    {-0.02798376941698385f,  0.18703481171888114f},
    {0.6308807679295904f,    0.030841381835986965f},
    {0.7148465705525415f,    -0.032883011666982945f},
    {0.23037781330885523f,   -0.010597401784997278f}};

typedef unsigned long long u64;
__device__ __forceinline__ u64 ffma2(u64 a, u64 b, u64 c) {
    u64 d;
    asm("fma.rn.f32x2 %0, %1, %2, %3;" : "=l"(d) : "l"(a), "l"(b), "l"(c));
    return d;
}
__device__ __forceinline__ u64 pk2(float x, float y) {
    u64 r;
    asm("mov.b64 %0, {%1, %2};" : "=l"(r) : "f"(x), "f"(y));
    return r;
}
__device__ __forceinline__ float2 up2(u64 v) {
    float2 r;
    asm("mov.b64 {%0, %1}, %2;" : "=f"(r.x), "=f"(r.y) : "l"(v));
    return r;
}

// Scratch (static device globals; allocation-free per harness rules)
__device__ __align__(256) float g_a2[(size_t)R_TOT * M2P];   // fwd a2, later a2-recon
__device__ __align__(256) float g_d2[(size_t)R_TOT * M2P];
__device__ __align__(256) float g_d3[(size_t)R_TOT * M3P];
__device__ __align__(256) float g_a4[(size_t)R_TOT * M4P];
__device__ __align__(256) float g_d4[(size_t)R_TOT * M4P];
__device__ __align__(256) float g_a4t[(size_t)M4 * R_TOT];   // [k][row]
__device__ __align__(256) float g_d4t[(size_t)M4 * R_TOT];
__device__ __align__(256) float g_a4mt[(size_t)M4 * R_TOT];  // mix out, [k][row]
__device__ __align__(256) float g_d4mt[(size_t)M4 * R_TOT];
__device__ __align__(256) float g_wt1[(size_t)M4 * CB * CB]; // [k][i*64+o]
__device__ __align__(256) float g_wt2[(size_t)M4 * CB * CB];

// ---------------------------------------------------------------------------
// K1: fused transpose + DWT L1 + L2 (halo recompute). a1 only in SMEM.
// ---------------------------------------------------------------------------
__device__ __forceinline__ void dwt12_a1_body(
    int cc, int kk, int K0,
    const float* __restrict__ xe, const float* __restrict__ xo,
    float* __restrict__ ae, float* __restrict__ ao) {
    int k1 = 2 * K0 - 6 + kk;
    if (k1 < 0 || k1 >= M1) return;
    const float* pe = &xe[cc * 139 + kk + 3];
    const float* po = &xo[cc * 139 + kk + 3];
    float s = 0.f;
#pragma unroll
    for (int t = 0; t < 4; t++)
        s = fmaf(po[-t], c_dlo[2 * t], fmaf(pe[-t], c_dlo[2 * t + 1], s));
    int tl = (k1 >> 1) - (K0 - 3);
    if (k1 & 1) ao[cc * 68 + tl] = s;
    else        ae[cc * 68 + tl] = s;
}

__global__ __launch_bounds__(256) void dwt12_kernel(const float* __restrict__ x,
                                                    float* __restrict__ a2,
                                                    float* __restrict__ d2) {
    extern __shared__ float sm[];
    float* xe = sm;                 // [32][139]
    float* xo = sm + 32 * 139;      // [32][139]
    float* ae = sm + 2 * 32 * 139;  // [32][68]
    float* ao = ae + 32 * 68;       // [32][68]
    int K0 = blockIdx.x * 64;
    int ct = blockIdx.y;
    int b = ct >> 1, c0 = (ct & 1) * 32;
    int tid = threadIdx.x;
    int xbase = 4 * K0 - 18;        // even
    const u64* lh = reinterpret_cast<const u64*>(c_lh);

    // x window via float4 over channels: 276 rows x 8 cgroups
    for (int idx = tid; idx < 276 * 8; idx += 256) {
        int nn = idx >> 3, cg = idx & 7;
        int q = xbase + nn;
        q = (q < 0) ? (-1 - q) : q;
        q = (q >= N0) ? (2 * N0 - 1 - q) : q;
        float4 v = __ldg(reinterpret_cast<const float4*>(&x[((size_t)b * N0 + q) * CB + c0 + cg * 4]));
        int u = nn >> 1;
        float* dst = (nn & 1) ? xo : xe;
        int cb4 = cg * 4;
        dst[(cb4 + 0) * 139 + u] = v.x;
        dst[(cb4 + 1) * 139 + u] = v.y;
        dst[(cb4 + 2) * 139 + u] = v.z;
        dst[(cb4 + 3) * 139 + u] = v.w;
    }
    __syncthreads();

    // a1 window [2K0-6, 2K0+127] (kk 0..133): pow2 main loop + tail
    for (int idx = tid; idx < 32 * 128; idx += 256) {
        dwt12_a1_body(idx >> 7, idx & 127, K0, xe, xo, ae, ao);
    }
    {   // tail kk 128..133
        int cc = tid >> 3, kk = 128 + (tid & 7);
        if (kk < 134) dwt12_a1_body(cc, kk, K0, xe, xo, ae, ao);
    }
    __syncthreads();

    // level 2
    for (int idx = tid; idx < 32 * 64; idx += 256) {
        int cc = idx >> 6, kk2 = idx & 63;
        int k2 = K0 + kk2;
        if (k2 >= M2) continue;
        float sa, sd;
        if (k2 >= 3 && k2 <= 2048) {
            const float* pe = &ae[cc * 68 + kk2 + 3];
            const float* po = &ao[cc * 68 + kk2 + 3];
            u64 acc = 0ull;
#pragma unroll
            for (int s = 0; s < 4; s++) {
                float vo = po[-s], ve = pe[-s];
                acc = ffma2(pk2(vo, vo), lh[2 * s], acc);
                acc = ffma2(pk2(ve, ve), lh[2 * s + 1], acc);
            }
            float2 ad = up2(acc);
            sa = ad.x; sd = ad.y;
        } else {
            sa = 0.f; sd = 0.f;
#pragma unroll
            for (int j = 0; j < 8; j++) {
                int g = 2 * k2 + 1 - j;
                g = (g < 0) ? (-1 - g) : g;
                g = (g >= M1) ? (2 * M1 - 1 - g) : g;
                int tl = (g >> 1) - (K0 - 3);
                float v = (g & 1) ? ao[cc * 68 + tl] : ae[cc * 68 + tl];
                sa = fmaf(v, c_dlo[j], sa);
                sd = fmaf(v, c_dhi[j], sd);
            }
        }
        size_t off = (size_t)(b * 64 + c0 + cc) * M2P + k2;
        a2[off] = sa;
        d2[off] = sd;
    }
}

// ---------------------------------------------------------------------------
// K2: fused DWT L3 + L4 per row. a3 only in SMEM.
// ---------------------------------------------------------------------------
__global__ __launch_bounds__(256) void dwt34_kernel(const float* __restrict__ a2,
                                                    float* __restrict__ d3,
                                                    float* __restrict__ a4,
                                                    float* __restrict__ d4) {
    __shared__ __align__(16) float s2e[1032];
    __shared__ __align__(16) float s2o[1032];
    __shared__ __align__(16) float a3e[520];
    __shared__ __align__(16) float a3o[520];
    int row = blockIdx.x, tid = threadIdx.x;
    const u64* lh = reinterpret_cast<const u64*>(c_lh);
    const float4* s4 = reinterpret_cast<const float4*>(a2 + (size_t)row * M2P);
    for (int i = tid; i < 514; i += 256) {
        float4 v = __ldg(&s4[i]);
        int u = 2 * i;
        s2e[u] = v.x; s2o[u] = v.y; s2e[u + 1] = v.z; s2o[u + 1] = v.w;
    }
    __syncthreads();
    float* d3r = d3 + (size_t)row * M3P;
    for (int k = tid; k < M3; k += 256) {
        float sa, sd;
        if (k >= 3 && k <= 1025) {
            u64 acc = 0ull;
#pragma unroll
            for (int s = 0; s < 4; s++) {
                float vo = s2o[k - s], ve = s2e[k - s];
                acc = ffma2(pk2(vo, vo), lh[2 * s], acc);
                acc = ffma2(pk2(ve, ve), lh[2 * s + 1], acc);
            }
            float2 ad = up2(acc);
            sa = ad.x; sd = ad.y;
        } else {
            sa = 0.f; sd = 0.f;
#pragma unroll
            for (int j = 0; j < 8; j++) {
                int g = 2 * k + 1 - j;
                g = (g < 0) ? (-1 - g) : g;
                g = (g >= M2) ? (2 * M2 - 1 - g) : g;
                float v = (g & 1) ? s2o[g >> 1] : s2e[g >> 1];
                sa = fmaf(v, c_dlo[j], sa);
                sd = fmaf(v, c_dhi[j], sd);
            }
        }
        if (k & 1) a3o[k >> 1] = sa; else a3e[k >> 1] = sa;
        d3r[k] = sd;
    }
    __syncthreads();
    float* a4r = a4 + (size_t)row * M4P;
    float* d4r = d4 + (size_t)row * M4P;
    for (int k = tid; k < M4; k += 256) {
        float sa, sd;
        if (k >= 3 && k <= 514) {
            u64 acc = 0ull;
#pragma unroll
            for (int s = 0; s < 4; s++) {
                float vo = a3o[k - s], ve = a3e[k - s];
                acc = ffma2(pk2(vo, vo), lh[2 * s], acc);
                acc = ffma2(pk2(ve, ve), lh[2 * s + 1], acc);
            }
            float2 ad = up2(acc);
            sa = ad.x; sd = ad.y;
        } else {
            sa = 0.f; sd = 0.f;
#pragma unroll
            for (int j = 0; j < 8; j++) {
                int g = 2 * k + 1 - j;
                g = (g < 0) ? (-1 - g) : g;
                g = (g >= M3) ? (2 * M3 - 1 - g) : g;
                float v = (g & 1) ? a3o[g >> 1] : a3e[g >> 1];
                sa = fmaf(v, c_dlo[j], sa);
                sd = fmaf(v, c_dhi[j], sd);
            }
        }
        a4r[k] = sa;
        d4r[k] = sd;
    }
}

// ---------------------------------------------------------------------------
// Forward transposes (z=0: a4->a4t, 1: d4->d4t, 2: w1->wt1, 3: w2->wt2)
// ---------------------------------------------------------------------------
__global__ void tr4_kernel(const float* __restrict__ s0, const float* __restrict__ s1,
                           const float* __restrict__ s2, const float* __restrict__ s3,
                           float* __restrict__ o0, float* __restrict__ o1,
                           float* __restrict__ o2, float* __restrict__ o3) {
    __shared__ float tile[32][33];
    int z = blockIdx.z;
    const float* __restrict__ src; float* __restrict__ dst; int R, ss, ds;
    if (z == 0)      { src = s0; dst = o0; R = R_TOT; ss = M4P; ds = R_TOT; }
    else if (z == 1) { src = s1; dst = o1; R = R_TOT; ss = M4P; ds = R_TOT; }
    else if (z == 2) { src = s2; dst = o2; R = 4096;  ss = M4;  ds = 4096; }
    else             { src = s3; dst = o3; R = 4096;  ss = M4;  ds = 4096; }
    int c0 = blockIdx.x * 32;
    int r0 = blockIdx.y * 32;
    if (r0 >= R) return;
    int tx = threadIdx.x, ty = threadIdx.y;
#pragma unroll
    for (int i = 0; i < 32; i += 8) {
        int r = r0 + ty + i, c = c0 + tx;
        if (r < R && c < M4) tile[ty + i][tx] = src[(size_t)r * ss + c];
    }
    __syncthreads();
#pragma unroll
    for (int i = 0; i < 32; i += 8) {
        int c = c0 + ty + i, r = r0 + tx;
        if (c < M4 && r < R) dst[(size_t)c * ds + r] = tile[tx][ty + i];
    }
}

// ---------------------------------------------------------------------------
// Channel mix v3: block = 2 k-slices; thread = 4 batches x 1 o-quad.
// One 16B w-LDS feeds 8 FFMA2 (halved w-LDS traffic vs v2).
// ---------------------------------------------------------------------------
__global__ __launch_bounds__(256) void mix_kernel(
    const float* __restrict__ a4t, const float* __restrict__ d4t,
    const float* __restrict__ wt1, const float* __restrict__ wt2,
    float* __restrict__ a4mt, float* __restrict__ d4mt) {
    int k0 = blockIdx.x * 2;
    const float* __restrict__ in = blockIdx.y ? d4t : a4t;
    const float* __restrict__ wt = blockIdx.y ? wt2 : wt1;
    float* __restrict__ out = blockIdx.y ? d4mt : a4mt;

    __shared__ __align__(16) float ws[2][4096];
    __shared__ __align__(16) float as[2][32 * 65];
    int tid = threadIdx.x;
    {
        const float4* wk4 = reinterpret_cast<const float4*>(wt + (size_t)k0 * 4096);
        float4* wsw = reinterpret_cast<float4*>(&ws[0][0]);
        for (int idx = tid; idx < 2048; idx += 256) {
            int ksl = idx >> 10, wi = idx & 1023;
            *reinterpret_cast<float4*>(&ws[ksl][wi * 4]) = __ldg(&wk4[ksl * 1024 + wi]);
        }
        (void)wsw;
        const float4* ik4 = reinterpret_cast<const float4*>(in + (size_t)k0 * R_TOT);
        for (int idx = tid; idx < 1024; idx += 256) {
            int ksl = idx >> 9, rest = idx & 511;
            float4 v = __ldg(&ik4[ksl * 512 + rest]);
            int b = rest >> 4, i = (rest & 15) * 4;
            float* p = &as[ksl][b * 65 + i];
            p[0] = v.x; p[1] = v.y; p[2] = v.z; p[3] = v.w;
        }
    }
    __syncthreads();

    int ks = tid >> 7;       // 0/1 k-slice
    int lt = tid & 127;
    int bg = lt >> 4;        // 0..7 -> batches {bg, bg+8, bg+16, bg+24}
    int lg = lt & 15;        // o-quad = lg*4
    const ulonglong2* wsu = reinterpret_cast<const ulonglong2*>(&ws[ks][0]);
    const float* asr = &as[ks][0];
    u64 acc[4][2] = {{0ull,0ull},{0ull,0ull},{0ull,0ull},{0ull,0ull}};
#pragma unroll 4
    for (int i = 0; i < 64; i++) {
        ulonglong2 w = wsu[i * 16 + lg];
#pragma unroll
        for (int h = 0; h < 4; h++) {
            float av = asr[(bg + 8 * h) * 65 + i];
            u64 p = pk2(av, av);
            acc[h][0] = ffma2(p, w.x, acc[h][0]);
            acc[h][1] = ffma2(p, w.y, acc[h][1]);
        }
    }
    float* ob = out + (size_t)(k0 + ks) * R_TOT;
#pragma unroll
    for (int h = 0; h < 4; h++) {
        float2 e0 = up2(acc[h][0]), e1 = up2(acc[h][1]);
        *reinterpret_cast<float4*>(ob + (bg + 8 * h) * 64 + lg * 4) =
            make_float4(e0.x, e0.y, e1.x, e1.y);
    }
}

// ---------------------------------------------------------------------------
// K6: fused transpose-back + IDWT L4->3 + L3->2. 4 consecutive rows per block;
// a4mt/d4mt columns loaded as aligned LDG.128 (row0 % 4 == 0). Writes a2r.
// Dynamic SMEM: 12416 floats = 49664 B.
// ---------------------------------------------------------------------------
__global__ __launch_bounds__(256) void idwt432_kernel(const float* __restrict__ a4mt,
                                                      const float* __restrict__ d4mt,
                                                      const float* __restrict__ d3,
                                                      float* __restrict__ a2r) {
    extern __shared__ float smi[];
    float* sa4 = smi;              // [4][520]
    float* sd4 = sa4 + 4 * 520;    // [4][520]
    float* sa3 = sd4 + 4 * 520;    // [4][1032]
    float* sd3 = sa3 + 4 * 1032;   // [4][1032]
    int row0 = blockIdx.x * 4;
    int tid = threadIdx.x;
    const u64* lh = reinterpret_cast<const u64*>(c_lh);

    // transpose-load a4mt/d4mt columns: one LDG.128 covers 4 rows at k
    for (int k = tid; k < M4; k += 256) {
        float4 va = __ldg(reinterpret_cast<const float4*>(a4mt + (size_t)k * R_TOT + row0));
        float4 vd = __ldg(reinterpret_cast<const float4*>(d4mt + (size_t)k * R_TOT + row0));
        sa4[0 * 520 + k] = va.x; sa4[1 * 520 + k] = va.y;
        sa4[2 * 520 + k] = va.z; sa4[3 * 520 + k] = va.w;
        sd4[0 * 520 + k] = vd.x; sd4[1 * 520 + k] = vd.y;
        sd4[2 * 520 + k] = vd.z; sd4[3 * 520 + k] = vd.w;
    }
    // d3 rows (coalesced float4)
#pragma unroll
    for (int j = 0; j < 4; j++) {
        const float4* p3 = reinterpret_cast<const float4*>(d3 + (size_t)(row0 + j) * M3P);
        for (int i = tid; i < 258; i += 256)
            *reinterpret_cast<float4*>(&sd3[j * 1032 + 4 * i]) = __ldg(&p3[i]);
    }
    __syncthreads();

    // L4 -> L3 (per row j)
#pragma unroll
    for (int j = 0; j < 4; j++) {
        const float* A = &sa4[j * 520];
        const float* D = &sd4[j * 520];
        float* O = &sa3[j * 1032];
        for (int q = tid; q < (M3 + 1) / 2; q += 256) {
            u64 accE = 0ull, accO = 0ull;
#pragma unroll
            for (int t = 0; t < 4; t++) {
                u64 ad = pk2(A[q + t], D[q + t]);
                accE = ffma2(ad, lh[2 * t + 1], accE);
                accO = ffma2(ad, lh[2 * t], accO);
            }
            float2 e = up2(accE), o = up2(accO);
            O[2 * q] = e.x + e.y;
            if (2 * q + 1 < M3) O[2 * q + 1] = o.x + o.y;
        }
    }
    __syncthreads();

    // L3 -> L2 (per row j) -> gmem
#pragma unroll
    for (int j = 0; j < 4; j++) {
        const float* A = &sa3[j * 1032];
        const float* D = &sd3[j * 1032];
        float* outr = a2r + (size_t)(row0 + j) * M2P;
        for (int q = tid; q < (M2 + 1) / 2; q += 256) {
            u64 accE = 0ull, accO = 0ull;
#pragma unroll
            for (int t = 0; t < 4; t++) {
                u64 ad = pk2(A[q + t], D[q + t]);
                accE = ffma2(ad, lh[2 * t + 1], accE);
                accO = ffma2(ad, lh[2 * t], accO);
            }
            float2 e = up2(accE), o = up2(accO);
            outr[2 * q] = e.x + e.y;
            if (2 * q + 1 < M2) outr[2 * q + 1] = o.x + o.y;
        }
    }
}

// ---------------------------------------------------------------------------
// K7: fused IDWT L2->1 + L1->0 + transpose-back + dense (f32x2) + fast mish.
// d1 recomputed in-block from the extended x tile (R16 WIN).
// ---------------------------------------------------------------------------
__device__ __forceinline__ float mish_f(float v) {
    float e = __expf(v);
    float t = 1.f + e;
    float t2 = fmaf(t, t, 1.f);
    float n  = fmaf(t, t, -1.f);
    float r = v * __fdividef(n, t2);
    return (v > 20.f) ? v : r;
}

__global__ __launch_bounds__(256) void ifinal2_kernel(
    const float* __restrict__ a2r, const float* __restrict__ d2,
    const float* __restrict__ x, const float* __restrict__ dk,
    const float* __restrict__ bias, float* __restrict__ out) {
    extern __shared__ float sm[];
    float* xs  = sm;            // 78*65 = 5070
    float* ys  = xs + 5070;     // 4160
    float* sA  = ys + 4160;     // 2304
    float* sD  = sA + 2304;     // 2304
    float* sA2 = sD + 2304;     // 1408
    float* sD2 = sA2 + 1408;    // 1408
    float* bs  = sD2 + 1408;    // 64

    int b = blockIdx.y;
    int n0 = blockIdx.x * 64;
    int r0 = n0 >> 1;
    int q0 = r0 >> 1;
    int tid = threadIdx.x;
    const u64* lh = reinterpret_cast<const u64*>(c_lh);

    if (tid < 64) bs[tid] = __ldg(&bias[tid]);
    for (int idx = tid; idx < 64 * 21; idx += 256) {
        int c = idx / 21, i = idx - c * 21;
        size_t off = (size_t)(b * 64 + c) * M2P + q0 + i;
        sA2[c * 22 + i] = __ldg(&a2r[off]);
        sD2[c * 22 + i] = __ldg(&d2[off]);
    }
    {   // x window: 78 rows x 16 float4 groups, reflect-at-load
        const float4* xg = reinterpret_cast<const float4*>(x);
        for (int idx = tid; idx < 78 * 16; idx += 256) {
            int ln = idx >> 4, ig = idx & 15;
            int n = n0 - 6 + ln;
            n = (n < 0) ? (-1 - n) : n;
            n = (n >= N0) ? (2 * N0 - 1 - n) : n;
            float4 v = __ldg(&xg[((size_t)b * N0 + n) * 16 + ig]);
            float* p = &xs[ln * 65 + ig * 4];
            p[0] = v.x; p[1] = v.y; p[2] = v.z; p[3] = v.w;
        }
    }
    __syncthreads();

    // recompute d1 window from x
    for (int idx = tid; idx < 64 * 35; idx += 256) {
        int c = idx / 35, rr = idx - c * 35;
        const float* xp = &xs[(2 * rr) * 65 + c];
        float s = 0.f;
#pragma unroll
        for (int t = 0; t < 8; t++)
            s = fmaf(xp[t * 65], c_dhi[7 - t], s);
        sD[c * 36 + rr] = s;
    }

    // reconstruct a1 window
    for (int idx = tid; idx < 64 * 18; idx += 256) {
        int c = idx / 18, m = idx - c * 18;
        const float* A = &sA2[c * 22 + m];
        const float* D = &sD2[c * 22 + m];
        u64 accE = 0ull, accO = 0ull;
#pragma unroll
        for (int t = 0; t < 4; t++) {
            u64 ad = pk2(A[t], D[t]);
            accE = ffma2(ad, lh[2 * t + 1], accE);
            accO = ffma2(ad, lh[2 * t], accO);
        }
        float2 e = up2(accE), o = up2(accO);
        sA[c * 36 + 2 * m] = e.x + e.y;
        sA[c * 36 + 2 * m + 1] = o.x + o.y;
    }
    __syncthreads();

    // IDWT level 1 into ys[nn][c]
    for (int idx = tid; idx < 64 * 32; idx += 256) {
        int c = idx >> 5, m = idx & 31;
        const float* A = &sA[c * 36 + m];
        const float* D = &sD[c * 36 + m];
        u64 accE = 0ull, accO = 0ull;
#pragma unroll
        for (int t = 0; t < 4; t++) {
            u64 ad = pk2(A[t], D[t]);
            accE = ffma2(ad, lh[2 * t + 1], accE);
            accO = ffma2(ad, lh[2 * t], accO);
        }
        float2 e = up2(accE), o = up2(accO);
        ys[(2 * m) * 65 + c] = e.x + e.y;
        ys[(2 * m + 1) * 65 + c] = o.x + o.y;
    }
    __syncthreads();

    // dense shortcut + add + mish
    int nn = tid >> 3;
    int lg = tid & 7;
    int g = lg * 4;
    const ulonglong2* dk2 = reinterpret_cast<const ulonglong2*>(dk);
    u64 bi0 = pk2(bs[g], bs[g + 1]);
    u64 bi1 = pk2(bs[g + 2], bs[g + 3]);
    u64 bi2 = pk2(bs[g + 32], bs[g + 33]);
    u64 bi3 = pk2(bs[g + 34], bs[g + 35]);
    u64 a00 = bi0, a01 = bi1, a02 = bi2, a03 = bi3;
    u64 a10 = bi0, a11 = bi1, a12 = bi2, a13 = bi3;
    const float* xr0 = &xs[(nn + 6) * 65];
    const float* xr1 = &xs[(nn + 38) * 65];
#pragma unroll
    for (int i = 0; i < 64; i++) {
        float xv0 = xr0[i];
        float xv1 = xr1[i];
        u64 p0 = pk2(xv0, xv0), p1 = pk2(xv1, xv1);
        ulonglong2 w0 = __ldg(&dk2[i * 16 + lg]);
        ulonglong2 w1 = __ldg(&dk2[i * 16 + 8 + lg]);
        a00 = ffma2(p0, w0.x, a00); a01 = ffma2(p0, w0.y, a01);
        a02 = ffma2(p0, w1.x, a02); a03 = ffma2(p0, w1.y, a03);
        a10 = ffma2(p1, w0.x, a10); a11 = ffma2(p1, w0.y, a11);
        a12 = ffma2(p1, w1.x, a12); a13 = ffma2(p1, w1.y, a13);
    }
#pragma unroll
    for (int h = 0; h < 2; h++) {
        int row = nn + h * 32;
        float2 q0_ = up2(h ? a10 : a00), q1_ = up2(h ? a11 : a01);
        float2 q2_ = up2(h ? a12 : a02), q3_ = up2(h ? a13 : a03);
        float v0[4] = {q0_.x, q0_.y, q1_.x, q1_.y};
        float v1[4] = {q2_.x, q2_.y, q3_.x, q3_.y};
#pragma unroll
        for (int u = 0; u < 4; u++) {
            v0[u] = mish_f(v0[u] + ys[row * 65 + g + u]);
            v1[u] = mish_f(v1[u] + ys[row * 65 + g + 32 + u]);
        }
        float4* op = reinterpret_cast<float4*>(&out[((size_t)b * N0 + n0 + row) * CB]);
        op[lg] = make_float4(v0[0], v0[1], v0[2], v0[3]);
        op[8 + lg] = make_float4(v1[0], v1[1], v1[2], v1[3]);
    }
}

// ---------------------------------------------------------------------------
extern "C" void kernel_launch(void* const* d_in, const int* in_sizes, int n_in,
                              void* d_out, int out_size) {
    (void)in_sizes; (void)n_in; (void)out_size;
    const float* x    = (const float*)d_in[0];
    const float* w1   = (const float*)d_in[1];
    const float* w2   = (const float*)d_in[2];
    const float* dk   = (const float*)d_in[3];
    const float* bias = (const float*)d_in[4];
    float* out = (float*)d_out;

    float *a2, *d2, *d3, *a4, *d4;
    float *a4t, *d4t, *a4mt, *d4mt, *wt1, *wt2;
    cudaGetSymbolAddress((void**)&a2,   g_a2);
    cudaGetSymbolAddress((void**)&d2,   g_d2);
    cudaGetSymbolAddress((void**)&d3,   g_d3);
    cudaGetSymbolAddress((void**)&a4,   g_a4);
    cudaGetSymbolAddress((void**)&d4,   g_d4);
    cudaGetSymbolAddress((void**)&a4t,  g_a4t);
    cudaGetSymbolAddress((void**)&d4t,  g_d4t);
    cudaGetSymbolAddress((void**)&a4mt, g_a4mt);
    cudaGetSymbolAddress((void**)&d4mt, g_d4mt);
    cudaGetSymbolAddress((void**)&wt1,  g_wt1);
    cudaGetSymbolAddress((void**)&wt2,  g_wt2);

    const int K1_SMEM = (2 * 32 * 139 + 2 * 32 * 68) * (int)sizeof(float);  // 52992 B
    const int K6_SMEM = (4 * 520 * 2 + 4 * 1032 * 2) * (int)sizeof(float);  // 49664 B
    const int K7_SMEM = (5070 + 4160 + 2304 + 2304 + 1408 + 1408 + 64) * (int)sizeof(float); // 66872 B
    cudaFuncSetAttribute(dwt12_kernel, cudaFuncAttributeMaxDynamicSharedMemorySize, K1_SMEM);
    cudaFuncSetAttribute(idwt432_kernel, cudaFuncAttributeMaxDynamicSharedMemorySize, K6_SMEM);
    cudaFuncSetAttribute(ifinal2_kernel, cudaFuncAttributeMaxDynamicSharedMemorySize, K7_SMEM);

    dim3 trb(32, 8);
    // 1. fused transpose + DWT L1 + L2
    dwt12_kernel<<<dim3(33, 64), 256, K1_SMEM>>>(x, a2, d2);
    // 2. fused DWT L3 + L4
    dwt34_kernel<<<R_TOT, 256>>>(a2, d3, a4, d4);
    // 3. forward transposes
    tr4_kernel<<<dim3((M4 + 31) / 32, 4096 / 32, 4), trb>>>(a4, d4, w1, w2, a4t, d4t, wt1, wt2);
    // 4. channel mix (v3: 2 k-slices/block, 4 batches/thread)
    mix_kernel<<<dim3(M4 / 2, 2), 256>>>(a4t, d4t, wt1, wt2, a4mt, d4mt);
    // 5. fused transpose-back + IDWT L4->3->2 (tr2 eliminated)
    idwt432_kernel<<<R_TOT / 4, 256, K6_SMEM>>>(a4mt, d4mt, d3, a2);
    // 6. fused IDWT L2->1 + L1->0 + dense + mish
    ifinal2_kernel<<<dim3(N0 / 64, BB), 256, K7_SMEM>>>(a2, d2, x, dk, bias, out);
}